// round 6
// baseline (speedup 1.0000x reference)
#include <cuda_runtime.h>
#include <cuda_fp16.h>
#include <math.h>
#include <stdint.h>

#define D_MODEL 1024
#define D_FF    4096
#define BATCH   8
#define SEQ     2048
#define M_TOT   (BATCH * SEQ)   // 16384

// ---------------- scratch (allocation-free: __device__ globals) ----------------
__device__ __half g_Xh [(size_t)M_TOT * D_MODEL];    // 32 MB  fp16 X
__device__ __half g_H  [(size_t)M_TOT * D_FF];       // 128 MB fp16 expert H
__device__ __half g_H2 [(size_t)M_TOT * D_FF];       // 128 MB fp16 shared H
__device__ __half g_Wa [(size_t)5 * D_MODEL * D_FF]; // 40 MB  fp16 weights A
__device__ __half g_Wb [(size_t)5 * D_MODEL * D_FF]; // 40 MB  fp16 weights B
__device__ float  g_gin[BATCH * 2 * D_MODEL];        // gate input rows
__device__ float  g_W  [BATCH * 2];                  // gate weights

// ---------------- helpers ------------------------------------------------------
__device__ __forceinline__ uint32_t smem_u32(const void* p) {
    uint32_t a;
    asm("{ .reg .u64 t; cvta.to.shared.u64 t, %1; cvt.u32.u64 %0, t; }"
        : "=r"(a) : "l"(p));
    return a;
}

__device__ __forceinline__ float gelu_tanh(float x) {
    float x3 = x * x * x;
    return 0.5f * x * (1.f + tanhf(0.7978845608028654f * (x + 0.044715f * x3)));
}

__device__ __forceinline__ void cp_async16(uint32_t saddr, const void* gaddr) {
    asm volatile("cp.async.cg.shared.global [%0], [%1], 16;"
                 :: "r"(saddr), "l"(gaddr) : "memory");
}
#define CP_COMMIT() asm volatile("cp.async.commit_group;" ::: "memory")
#define CP_WAIT1()  asm volatile("cp.async.wait_group 1;" ::: "memory")

__device__ __forceinline__ void ldsm4(uint32_t* r, uint32_t addr) {
    asm volatile("ldmatrix.sync.aligned.m8n8.x4.shared.b16 {%0,%1,%2,%3}, [%4];"
                 : "=r"(r[0]), "=r"(r[1]), "=r"(r[2]), "=r"(r[3]) : "r"(addr));
}
__device__ __forceinline__ void ldsm4t(uint32_t* r, uint32_t addr) {
    asm volatile("ldmatrix.sync.aligned.m8n8.x4.trans.shared.b16 {%0,%1,%2,%3}, [%4];"
                 : "=r"(r[0]), "=r"(r[1]), "=r"(r[2]), "=r"(r[3]) : "r"(addr));
}
__device__ __forceinline__ void mma16816(float* d, const uint32_t* a, const uint32_t* b) {
    asm volatile(
        "mma.sync.aligned.m16n8k16.row.col.f32.f16.f16.f32 "
        "{%0,%1,%2,%3}, {%4,%5,%6,%7}, {%8,%9}, {%0,%1,%2,%3};"
        : "+f"(d[0]), "+f"(d[1]), "+f"(d[2]), "+f"(d[3])
        : "r"(a[0]), "r"(a[1]), "r"(a[2]), "r"(a[3]), "r"(b[0]), "r"(b[1]));
}

// ================================================================================
// Fused dual up-projection: H[tile] = gelu(X@B0) * (X@B1), fp16 out.
// CTA: 128 rows x 64 cols of BOTH GEMMs (A smem tile shared). K = D_MODEL = 1024.
// ================================================================================
#define UP_STAGE 32768     // A 16KB + B0 8KB + B1 8KB
#define UP_SMEM  (3 * UP_STAGE)

__device__ __forceinline__ void up_fill(uint32_t st, const __half* __restrict__ A,
                                        const __half* __restrict__ B0,
                                        const __half* __restrict__ B1,
                                        int rowBase, int colBase, int k0, int tid)
{
#pragma unroll
    for (int i = 0; i < 4; i++) {      // A: 128 rows x 8 chunks (row = 128B)
        int c = tid + i * 256;
        int row = c >> 3, kc = c & 7;
        uint32_t dst = st + (row << 7) + (((kc ^ row) & 7) << 4);
        cp_async16(dst, A + (size_t)(rowBase + row) * D_MODEL + k0 + (kc << 3));
    }
#pragma unroll
    for (int i = 0; i < 2; i++) {      // B0: 64 k-rows x 8 chunks (row = 128B)
        int c = tid + i * 256;
        int row = c >> 3, nc = c & 7;
        uint32_t dst = st + 16384 + (row << 7) + (((nc ^ row) & 7) << 4);
        cp_async16(dst, B0 + (size_t)(k0 + row) * D_FF + colBase + (nc << 3));
    }
#pragma unroll
    for (int i = 0; i < 2; i++) {      // B1
        int c = tid + i * 256;
        int row = c >> 3, nc = c & 7;
        uint32_t dst = st + 24576 + (row << 7) + (((nc ^ row) & 7) << 4);
        cp_async16(dst, B1 + (size_t)(k0 + row) * D_FF + colBase + (nc << 3));
    }
}

__global__ __launch_bounds__(256, 2)
void up_fused(const __half* __restrict__ A, const __half* __restrict__ B0w,
              const __half* __restrict__ B1w, __half* __restrict__ H,
              const int* __restrict__ labels)
{
    extern __shared__ char smem[];
    const uint32_t sb = smem_u32(smem);
    const int tid = threadIdx.x, lane = tid & 31, warp = tid >> 5;
    const int rowBase = blockIdx.y * 128, colBase = blockIdx.x * 64;
    size_t woff = labels ? (size_t)labels[rowBase / SEQ] * D_MODEL * D_FF : 0;
    const __half* B0 = B0w + woff;
    const __half* B1 = B1w + woff;

    const int wm = (warp >> 1) * 32, wn = (warp & 1) * 32;
    const int lr = lane >> 2, lc = lane & 3;
    const int hi = lane >> 4;

    float acc[2][2][4][4];   // [matrix][mt][nt][reg]
#pragma unroll
    for (int m = 0; m < 2; m++)
#pragma unroll
        for (int mt = 0; mt < 2; mt++)
#pragma unroll
            for (int nt = 0; nt < 4; nt++)
#pragma unroll
                for (int i = 0; i < 4; i++) acc[m][mt][nt][i] = 0.f;

    const int aRow = wm + (lane & 15);
    const uint32_t aOff = (uint32_t)aRow << 7;
    const uint32_t a_r7 = aRow & 7;
    const uint32_t bRowOff = (uint32_t)(lane & 15) << 7;
    const uint32_t b_r7 = lane & 7;
    uint32_t ncSw[2];
#pragma unroll
    for (int p = 0; p < 2; p++) {
        int nchunk = (wn >> 3) + p * 2 + hi;
        ncSw[p] = (uint32_t)((nchunk ^ b_r7) & 7) << 4;
    }

    const int T = D_MODEL / 64;  // 16 stages
    up_fill(sb, A, B0, B1, rowBase, colBase, 0, tid);            CP_COMMIT();
    up_fill(sb + UP_STAGE, A, B0, B1, rowBase, colBase, 64, tid); CP_COMMIT();

    int buf = 0;
    for (int t = 0; t < T; t++) {
        CP_WAIT1();
        __syncthreads();
        const uint32_t base  = sb + (uint32_t)buf * UP_STAGE;
        const uint32_t aBase = base + aOff;

        const int tn = t + 2;
        if (tn < T) {
            int nb = buf + 2; if (nb >= 3) nb -= 3;
            up_fill(sb + (uint32_t)nb * UP_STAGE, A, B0, B1,
                    rowBase, colBase, tn * 64, tid);
        }
        CP_COMMIT();

#pragma unroll
        for (int ks = 0; ks < 4; ks++) {
            uint32_t a[2][4], b[2][2][4];
            const uint32_t csw = (uint32_t)(((ks * 2 + hi) ^ (int)a_r7) << 4);
            ldsm4(a[0], aBase + csw);
            ldsm4(a[1], aBase + (16u << 7) + csw);
            const uint32_t bk = base + 16384 + bRowOff + (uint32_t)ks * 2048;
#pragma unroll
            for (int m = 0; m < 2; m++)
#pragma unroll
                for (int p = 0; p < 2; p++)
                    ldsm4t(b[m][p], bk + (uint32_t)m * 8192 + ncSw[p]);
#pragma unroll
            for (int m = 0; m < 2; m++)
#pragma unroll
                for (int mt = 0; mt < 2; mt++)
#pragma unroll
                    for (int nt = 0; nt < 4; nt++)
                        mma16816(acc[m][mt][nt], a[mt],
                                 &b[m][nt >> 1][(nt & 1) * 2]);
        }
        buf++; if (buf == 3) buf = 0;
    }

    // ---- epilogue: H = half(gelu(acc0) * acc1) ----
#pragma unroll
    for (int mt = 0; mt < 2; mt++) {
        const int r0 = rowBase + wm + mt * 16 + lr;
#pragma unroll
        for (int nt = 0; nt < 4; nt++) {
            const int c = colBase + wn + nt * 8 + lc * 2;
            const size_t i0 = (size_t)r0 * D_FF + c;
            const size_t i1 = i0 + (size_t)8 * D_FF;
            float v0 = gelu_tanh(acc[0][mt][nt][0]) * acc[1][mt][nt][0];
            float v1 = gelu_tanh(acc[0][mt][nt][1]) * acc[1][mt][nt][1];
            float v2 = gelu_tanh(acc[0][mt][nt][2]) * acc[1][mt][nt][2];
            float v3 = gelu_tanh(acc[0][mt][nt][3]) * acc[1][mt][nt][3];
            *(__half2*)(H + i0) = __floats2half2_rn(v0, v1);
            *(__half2*)(H + i1) = __floats2half2_rn(v2, v3);
        }
    }
}

// ================================================================================
// Down GEMM: out(+)= w[b]*(H @ Wo), K = D_FF = 4096, N = D_MODEL, fp32 out.
// ================================================================================
#define DN_ABYTES 16384
#define DN_STAGE  32768
#define DN_SMEM   (3 * DN_STAGE)

__device__ __forceinline__ void dn_fill(uint32_t st, const __half* __restrict__ A,
                                        const __half* __restrict__ Bp,
                                        int rowBase, int colBase, int k0, int tid)
{
#pragma unroll
    for (int i = 0; i < 4; i++) {      // A: 128 rows x 8 chunks (row = 128B)
        int c = tid + i * 256;
        int row = c >> 3, kc = c & 7;
        uint32_t dst = st + (row << 7) + (((kc ^ row) & 7) << 4);
        cp_async16(dst, A + (size_t)(rowBase + row) * D_FF + k0 + (kc << 3));
    }
#pragma unroll
    for (int i = 0; i < 4; i++) {      // B: 64 k-rows x 16 chunks (row = 256B)
        int c = tid + i * 256;
        int row = c >> 4, nc = c & 15;
        uint32_t dst = st + DN_ABYTES + (row << 8) +
                       ((((nc ^ row) & 7) | (nc & 8)) << 4);
        cp_async16(dst, Bp + (size_t)(k0 + row) * D_MODEL + colBase + (nc << 3));
    }
}

template<int ADD>
__global__ __launch_bounds__(256, 2)
void dn_gemm(const __half* __restrict__ A, const __half* __restrict__ Bw,
             float* __restrict__ out, const int* __restrict__ labels,
             const float* __restrict__ w)
{
    extern __shared__ char smem[];
    const uint32_t sb = smem_u32(smem);
    const int tid = threadIdx.x, lane = tid & 31, warp = tid >> 5;
    const int rowBase = blockIdx.y * 128, colBase = blockIdx.x * 128;
    const int batch = rowBase / SEQ;
    const __half* Bp = Bw + (labels ? (size_t)labels[batch] * D_FF * D_MODEL : 0);

    const int wm = (warp >> 1) * 32, wn = (warp & 1) * 64;
    const int lr = lane >> 2, lc = lane & 3;
    const int hi = lane >> 4;

    float acc[2][8][4];
#pragma unroll
    for (int mt = 0; mt < 2; mt++)
#pragma unroll
        for (int nt = 0; nt < 8; nt++)
#pragma unroll
            for (int i = 0; i < 4; i++) acc[mt][nt][i] = 0.f;

    const int aRow = wm + (lane & 15);
    const uint32_t aOff = (uint32_t)aRow << 7;
    const uint32_t a_r7 = aRow & 7;
    const uint32_t bRowOff = (uint32_t)(lane & 15) << 8;
    const uint32_t b_r7 = lane & 7;
    uint32_t ncSw[4];
#pragma unroll
    for (int p = 0; p < 4; p++) {
        int nchunk = (wn >> 3) + p * 2 + hi;
        ncSw[p] = (uint32_t)((nchunk & 8) | ((nchunk ^ b_r7) & 7)) << 4;
    }

    const int T = D_FF / 64;  // 64 stages
    dn_fill(sb, A, Bp, rowBase, colBase, 0, tid);            CP_COMMIT();
    dn_fill(sb + DN_STAGE, A, Bp, rowBase, colBase, 64, tid); CP_COMMIT();

    int buf = 0;
    for (int t = 0; t < T; t++) {
        CP_WAIT1();
        __syncthreads();
        const uint32_t base  = sb + (uint32_t)buf * DN_STAGE;
        const uint32_t aBase = base + aOff;
        const uint32_t bBase = base + DN_ABYTES + bRowOff;

        const int tn = t + 2;
        if (tn < T) {
            int nb = buf + 2; if (nb >= 3) nb -= 3;
            dn_fill(sb + (uint32_t)nb * DN_STAGE, A, Bp,
                    rowBase, colBase, tn * 64, tid);
        }
        CP_COMMIT();

#pragma unroll
        for (int ks = 0; ks < 4; ks++) {
            uint32_t a[2][4], b[4][4];
            const uint32_t csw = (uint32_t)(((ks * 2 + hi) ^ (int)a_r7) << 4);
            ldsm4(a[0], aBase + csw);
            ldsm4(a[1], aBase + (16u << 7) + csw);
            const uint32_t bk = bBase + (uint32_t)ks * 4096;
#pragma unroll
            for (int p = 0; p < 4; p++) ldsm4t(b[p], bk + ncSw[p]);
#pragma unroll
            for (int mt = 0; mt < 2; mt++)
#pragma unroll
                for (int nt = 0; nt < 8; nt++)
                    mma16816(acc[mt][nt], a[mt], &b[nt >> 1][(nt & 1) * 2]);
        }
        buf++; if (buf == 3) buf = 0;
    }

    // ---- epilogue: out (+)= wv * acc ----
    const float wv = w[batch * 2 + ADD];
#pragma unroll
    for (int mt = 0; mt < 2; mt++) {
        const int r0 = rowBase + wm + mt * 16 + lr;
#pragma unroll
        for (int nt = 0; nt < 8; nt++) {
            const int c = colBase + wn + nt * 8 + lc * 2;
            const size_t i0 = (size_t)r0 * D_MODEL + c;
            const size_t i1 = i0 + (size_t)8 * D_MODEL;
            float2 v0 = make_float2(wv * acc[mt][nt][0], wv * acc[mt][nt][1]);
            float2 v1 = make_float2(wv * acc[mt][nt][2], wv * acc[mt][nt][3]);
            if (ADD) {
                float2 p0 = *(float2*)(out + i0);
                float2 p1 = *(float2*)(out + i1);
                v0.x += p0.x; v0.y += p0.y; v1.x += p1.x; v1.y += p1.y;
            }
            *(float2*)(out + i0) = v0;
            *(float2*)(out + i1) = v1;
        }
    }
}

// ---------------- f32 -> f16 conversion ----------------------------------------
__global__ __launch_bounds__(256)
void cvt_f16(const float* __restrict__ in, __half* __restrict__ out, size_t n)
{
    size_t i = ((size_t)blockIdx.x * 256 + threadIdx.x) * 8;
    if (i >= n) return;
    float4 v0 = *(const float4*)(in + i);
    float4 v1 = *(const float4*)(in + i + 4);
    __half2* o = (__half2*)(out + i);
    o[0] = __floats2half2_rn(v0.x, v0.y);
    o[1] = __floats2half2_rn(v0.z, v0.w);
    o[2] = __floats2half2_rn(v1.x, v1.y);
    o[3] = __floats2half2_rn(v1.z, v1.w);
}

// ---------------- row-0 GEMV: gin[b][0:1024]=H_row0@Wo[lbl], [1024:2048]=H2row0@sWo
__global__ __launch_bounds__(256)
void row0_kernel(const __half* __restrict__ H, const __half* __restrict__ H2,
                 const __half* __restrict__ Wo, const __half* __restrict__ sWo,
                 const int* __restrict__ lbl, float* __restrict__ gin)
{
    const int b = blockIdx.y;
    const int j = blockIdx.x * 256 + threadIdx.x;   // 0..2047
    const bool sh = j >= D_MODEL;
    const int col = j & (D_MODEL - 1);
    const __half* A = (sh ? H2 : H) + (size_t)b * SEQ * D_FF;
    const __half* Wp = sh ? sWo : Wo + (size_t)lbl[b] * D_FF * D_MODEL;
    float acc = 0.f;
    for (int k = 0; k < D_FF; k++)
        acc = fmaf(__half2float(A[k]), __half2float(Wp[(size_t)k * D_MODEL + col]), acc);
    gin[b * 2 * D_MODEL + j] = acc;
}

// ---------------- gate ----------------------------------------------------------
__global__ __launch_bounds__(256)
void gate_kernel(const float* __restrict__ gin,
                 const float* __restrict__ g0, const float* __restrict__ g1,
                 float* __restrict__ w)
{
    int b = blockIdx.x;
    const float* gi = gin + b * 2 * D_MODEL;
    float h[4] = {0.f, 0.f, 0.f, 0.f};
    for (int k = 0; k < 2 * D_MODEL; k++) {
        float xin = gi[k];
        const float* grow = g0 + (size_t)k * D_MODEL;
#pragma unroll
        for (int u = 0; u < 4; u++)
            h[u] = fmaf(xin, grow[threadIdx.x + 256 * u], h[u]);
    }
    float l0 = 0.f, l1 = 0.f;
#pragma unroll
    for (int u = 0; u < 4; u++) {
        int j = threadIdx.x + 256 * u;
        float hr = fmaxf(h[u], 0.f);
        l0 = fmaf(hr, g1[j * 2 + 0], l0);
        l1 = fmaf(hr, g1[j * 2 + 1], l1);
    }
    __shared__ float red0[256], red1[256];
    red0[threadIdx.x] = l0;
    red1[threadIdx.x] = l1;
    __syncthreads();
    for (int s = 128; s > 0; s >>= 1) {
        if (threadIdx.x < s) {
            red0[threadIdx.x] += red0[threadIdx.x + s];
            red1[threadIdx.x] += red1[threadIdx.x + s];
        }
        __syncthreads();
    }
    if (threadIdx.x == 0) {
        float a = red0[0], c = red1[0];
        float m  = fmaxf(a, c);
        float e0 = expf(a - m), e1 = expf(c - m);
        float inv = 1.f / (e0 + e1);
        w[b * 2 + 0] = e0 * inv;
        w[b * 2 + 1] = e1 * inv;
    }
}

// ---------------- launch -------------------------------------------------------
extern "C" void kernel_launch(void* const* d_in, const int* in_sizes, int n_in,
                              void* d_out, int out_size)
{
    const float* X    = (const float*)d_in[0];
    const int*   lbl  = (const int*)  d_in[1];
    const float* Wi0  = (const float*)d_in[2];
    const float* Wi1  = (const float*)d_in[3];
    const float* Wo   = (const float*)d_in[4];
    const float* sWi0 = (const float*)d_in[5];
    const float* sWi1 = (const float*)d_in[6];
    const float* sWo  = (const float*)d_in[7];
    const float* G0   = (const float*)d_in[8];
    const float* G1   = (const float*)d_in[9];
    float* out = (float*)d_out;

    __half *Xh, *H, *H2, *Wa, *Wb;
    float *gin, *W;
    cudaGetSymbolAddress((void**)&Xh,  g_Xh);
    cudaGetSymbolAddress((void**)&H,   g_H);
    cudaGetSymbolAddress((void**)&H2,  g_H2);
    cudaGetSymbolAddress((void**)&Wa,  g_Wa);
    cudaGetSymbolAddress((void**)&Wb,  g_Wb);
    cudaGetSymbolAddress((void**)&gin, g_gin);
    cudaGetSymbolAddress((void**)&W,   g_W);

    cudaFuncSetAttribute(up_fused, cudaFuncAttributeMaxDynamicSharedMemorySize, UP_SMEM);
    cudaFuncSetAttribute(dn_gemm<0>, cudaFuncAttributeMaxDynamicSharedMemorySize, DN_SMEM);
    cudaFuncSetAttribute(dn_gemm<1>, cudaFuncAttributeMaxDynamicSharedMemorySize, DN_SMEM);

    const size_t nX  = (size_t)M_TOT * D_MODEL;
    const size_t nWe = (size_t)5 * D_MODEL * D_FF;
    const size_t nWs = (size_t)D_MODEL * D_FF;
    dim3 blk(256);
    dim3 grid_up(D_FF / 64, M_TOT / 128);     // (64,128)
    dim3 grid_dn(D_MODEL / 128, M_TOT / 128); // (8,128)

    cvt_f16<<<(unsigned)(nX / 2048), blk>>>(X, Xh, nX);

    // ---- expert up (fused Wi0+Wi1 -> H) ----
    cvt_f16<<<(unsigned)(nWe / 2048), blk>>>(Wi0, Wa, nWe);
    cvt_f16<<<(unsigned)(nWe / 2048), blk>>>(Wi1, Wb, nWe);
    up_fused<<<grid_up, blk, UP_SMEM>>>(Xh, Wa, Wb, H, lbl);

    // ---- shared up (fused sWi0+sWi1 -> H2) ----
    cvt_f16<<<(unsigned)(nWs / 2048), blk>>>(sWi0, Wa, nWs);
    cvt_f16<<<(unsigned)(nWs / 2048), blk>>>(sWi1, Wb, nWs);
    up_fused<<<grid_up, blk, UP_SMEM>>>(Xh, Wa, Wb, H2, nullptr);

    // ---- down weights, gate from first-token rows ----
    cvt_f16<<<(unsigned)(nWe / 2048), blk>>>(Wo, Wa, nWe);
    cvt_f16<<<(unsigned)(nWs / 2048), blk>>>(sWo, Wb, nWs);
    row0_kernel<<<dim3(8, BATCH), blk>>>(H, H2, Wa, Wb, lbl, gin);
    gate_kernel<<<BATCH, blk>>>(gin, G0, G1, W);

    // ---- down GEMMs with gate weights fused; out = w0*expert + w1*shared ----
    dn_gemm<0><<<grid_dn, blk, DN_SMEM>>>(H, Wa, out, lbl, W);
    dn_gemm<1><<<grid_dn, blk, DN_SMEM>>>(H2, Wb, out, nullptr, W);
}

// round 7
// speedup vs baseline: 1.0203x; 1.0203x over previous
#include <cuda_runtime.h>
#include <cuda_fp16.h>
#include <math.h>
#include <stdint.h>

#define D_MODEL 1024
#define D_FF    4096
#define BATCH   8
#define SEQ     2048
#define M_TOT   (BATCH * SEQ)   // 16384
#define WSLOT   ((size_t)D_MODEL * D_FF)   // 4194304 elems per weight slot

// ---------------- scratch (allocation-free: __device__ globals) ----------------
__device__ __half g_Xh [(size_t)M_TOT * D_MODEL];  // 32 MB  fp16 X
__device__ __half g_H  [(size_t)M_TOT * D_FF];     // 128 MB fp16 expert H
__device__ __half g_H2 [(size_t)M_TOT * D_FF];     // 128 MB fp16 shared H
__device__ __half g_Wa [6 * WSLOT];                // 48 MB  Wi0[0:5], sWi0[5]
__device__ __half g_Wb [6 * WSLOT];                // 48 MB  Wi1[0:5], sWi1[5]
__device__ __half g_Wc [6 * WSLOT];                // 48 MB  Wo [0:5], sWo [5]
__device__ float  g_gp [4 * BATCH * 2 * D_MODEL];  // row0 partials (k-split 4)
__device__ float  g_W  [BATCH * 2];                // gate weights

// ---------------- helpers ------------------------------------------------------
__device__ __forceinline__ uint32_t smem_u32(const void* p) {
    uint32_t a;
    asm("{ .reg .u64 t; cvta.to.shared.u64 t, %1; cvt.u32.u64 %0, t; }"
        : "=r"(a) : "l"(p));
    return a;
}

__device__ __forceinline__ float gelu_tanh(float x) {
    float x3 = x * x * x;
    return 0.5f * x * (1.f + tanhf(0.7978845608028654f * (x + 0.044715f * x3)));
}

__device__ __forceinline__ void cp_async16(uint32_t saddr, const void* gaddr) {
    asm volatile("cp.async.cg.shared.global [%0], [%1], 16;"
                 :: "r"(saddr), "l"(gaddr) : "memory");
}
#define CP_COMMIT() asm volatile("cp.async.commit_group;" ::: "memory")
#define CP_WAIT1()  asm volatile("cp.async.wait_group 1;" ::: "memory")
#define CP_WAIT0()  asm volatile("cp.async.wait_group 0;" ::: "memory")

__device__ __forceinline__ void ldsm4(uint32_t* r, uint32_t addr) {
    asm volatile("ldmatrix.sync.aligned.m8n8.x4.shared.b16 {%0,%1,%2,%3}, [%4];"
                 : "=r"(r[0]), "=r"(r[1]), "=r"(r[2]), "=r"(r[3]) : "r"(addr));
}
__device__ __forceinline__ void ldsm4t(uint32_t* r, uint32_t addr) {
    asm volatile("ldmatrix.sync.aligned.m8n8.x4.trans.shared.b16 {%0,%1,%2,%3}, [%4];"
                 : "=r"(r[0]), "=r"(r[1]), "=r"(r[2]), "=r"(r[3]) : "r"(addr));
}
__device__ __forceinline__ void mma16816(float* d, const uint32_t* a, const uint32_t* b) {
    asm volatile(
        "mma.sync.aligned.m16n8k16.row.col.f32.f16.f16.f32 "
        "{%0,%1,%2,%3}, {%4,%5,%6,%7}, {%8,%9}, {%0,%1,%2,%3};"
        : "+f"(d[0]), "+f"(d[1]), "+f"(d[2]), "+f"(d[3])
        : "r"(a[0]), "r"(a[1]), "r"(a[2]), "r"(a[3]), "r"(b[0]), "r"(b[1]));
}

// ================================================================================
// Fused dual up-projection: H[tile] = gelu(X@B0) * (X@B1), fp16 out.
// CTA: 128 rows x 64 cols of BOTH GEMMs. z=0: expert -> H; z=1: shared -> H2.
// ================================================================================
#define UP_STAGE 32768     // A 16KB + B0 8KB + B1 8KB
#define UP_SMEM  (3 * UP_STAGE)

__device__ __forceinline__ void up_fill(uint32_t st, const __half* __restrict__ A,
                                        const __half* __restrict__ B0,
                                        const __half* __restrict__ B1,
                                        int rowBase, int colBase, int k0, int tid)
{
#pragma unroll
    for (int i = 0; i < 4; i++) {      // A: 128 rows x 8 chunks (row = 128B)
        int c = tid + i * 256;
        int row = c >> 3, kc = c & 7;
        uint32_t dst = st + (row << 7) + (((kc ^ row) & 7) << 4);
        cp_async16(dst, A + (size_t)(rowBase + row) * D_MODEL + k0 + (kc << 3));
    }
#pragma unroll
    for (int i = 0; i < 2; i++) {      // B0: 64 k-rows x 8 chunks
        int c = tid + i * 256;
        int row = c >> 3, nc = c & 7;
        uint32_t dst = st + 16384 + (row << 7) + (((nc ^ row) & 7) << 4);
        cp_async16(dst, B0 + (size_t)(k0 + row) * D_FF + colBase + (nc << 3));
    }
#pragma unroll
    for (int i = 0; i < 2; i++) {      // B1
        int c = tid + i * 256;
        int row = c >> 3, nc = c & 7;
        uint32_t dst = st + 24576 + (row << 7) + (((nc ^ row) & 7) << 4);
        cp_async16(dst, B1 + (size_t)(k0 + row) * D_FF + colBase + (nc << 3));
    }
}

__global__ __launch_bounds__(256, 2)
void up_fused(const __half* __restrict__ A, const __half* __restrict__ Wa,
              const __half* __restrict__ Wb, __half* __restrict__ He,
              __half* __restrict__ Hs, const int* __restrict__ labels)
{
    extern __shared__ char smem[];
    const uint32_t sb = smem_u32(smem);
    const int tid = threadIdx.x, lane = tid & 31, warp = tid >> 5;
    const int rowBase = blockIdx.y * 128, colBase = blockIdx.x * 64;
    const int slot = blockIdx.z ? 5 : labels[rowBase / SEQ];
    __half* H = blockIdx.z ? Hs : He;
    const __half* B0 = Wa + (size_t)slot * WSLOT;
    const __half* B1 = Wb + (size_t)slot * WSLOT;

    const int wm = (warp >> 1) * 32, wn = (warp & 1) * 32;
    const int lr = lane >> 2, lc = lane & 3;
    const int hi = lane >> 4;

    float acc[2][2][4][4];   // [matrix][mt][nt][reg]
#pragma unroll
    for (int m = 0; m < 2; m++)
#pragma unroll
        for (int mt = 0; mt < 2; mt++)
#pragma unroll
            for (int nt = 0; nt < 4; nt++)
#pragma unroll
                for (int i = 0; i < 4; i++) acc[m][mt][nt][i] = 0.f;

    const int aRow = wm + (lane & 15);
    const uint32_t aOff = (uint32_t)aRow << 7;
    const uint32_t a_r7 = aRow & 7;
    const uint32_t bRowOff = (uint32_t)(lane & 15) << 7;
    const uint32_t b_r7 = lane & 7;
    uint32_t ncSw[2];
#pragma unroll
    for (int p = 0; p < 2; p++) {
        int nchunk = (wn >> 3) + p * 2 + hi;
        ncSw[p] = (uint32_t)((nchunk ^ b_r7) & 7) << 4;
    }

    const int T = D_MODEL / 64;  // 16 stages
    up_fill(sb, A, B0, B1, rowBase, colBase, 0, tid);             CP_COMMIT();
    up_fill(sb + UP_STAGE, A, B0, B1, rowBase, colBase, 64, tid); CP_COMMIT();

    int buf = 0;
    for (int t = 0; t < T; t++) {
        CP_WAIT1();
        __syncthreads();
        const uint32_t base  = sb + (uint32_t)buf * UP_STAGE;
        const uint32_t aBase = base + aOff;

        const int tn = t + 2;
        if (tn < T) {
            int nb = buf + 2; if (nb >= 3) nb -= 3;
            up_fill(sb + (uint32_t)nb * UP_STAGE, A, B0, B1,
                    rowBase, colBase, tn * 64, tid);
        }
        CP_COMMIT();

#pragma unroll
        for (int ks = 0; ks < 4; ks++) {
            uint32_t a[2][4], b[2][2][4];
            const uint32_t csw = (uint32_t)(((ks * 2 + hi) ^ (int)a_r7) << 4);
            ldsm4(a[0], aBase + csw);
            ldsm4(a[1], aBase + (16u << 7) + csw);
            const uint32_t bk = base + 16384 + bRowOff + (uint32_t)ks * 2048;
#pragma unroll
            for (int m = 0; m < 2; m++)
#pragma unroll
                for (int p = 0; p < 2; p++)
                    ldsm4t(b[m][p], bk + (uint32_t)m * 8192 + ncSw[p]);
#pragma unroll
            for (int m = 0; m < 2; m++)
#pragma unroll
                for (int mt = 0; mt < 2; mt++)
#pragma unroll
                    for (int nt = 0; nt < 4; nt++)
                        mma16816(acc[m][mt][nt], a[mt],
                                 &b[m][nt >> 1][(nt & 1) * 2]);
        }
        buf++; if (buf == 3) buf = 0;
    }

    // ---- epilogue: H = half(gelu(acc0) * acc1) ----
#pragma unroll
    for (int mt = 0; mt < 2; mt++) {
        const int r0 = rowBase + wm + mt * 16 + lr;
#pragma unroll
        for (int nt = 0; nt < 4; nt++) {
            const int c = colBase + wn + nt * 8 + lc * 2;
            const size_t i0 = (size_t)r0 * D_FF + c;
            const size_t i1 = i0 + (size_t)8 * D_FF;
            float v0 = gelu_tanh(acc[0][mt][nt][0]) * acc[1][mt][nt][0];
            float v1 = gelu_tanh(acc[0][mt][nt][1]) * acc[1][mt][nt][1];
            float v2 = gelu_tanh(acc[0][mt][nt][2]) * acc[1][mt][nt][2];
            float v3 = gelu_tanh(acc[0][mt][nt][3]) * acc[1][mt][nt][3];
            *(__half2*)(H + i0) = __floats2half2_rn(v0, v1);
            *(__half2*)(H + i1) = __floats2half2_rn(v2, v3);
        }
    }
}

// ================================================================================
// Fused down GEMM: out = w0*(H@Wo[lbl]) + w1*(H2@sWo).
// Phase 0 accumulates E; acc *= w0/w1; phase 1 accumulates S; out = w1*acc.
// ================================================================================
#define DN_ABYTES 16384
#define DN_STAGE  32768
#define DN_SMEM   (3 * DN_STAGE)

__device__ __forceinline__ void dn_fill(uint32_t st, const __half* __restrict__ A,
                                        const __half* __restrict__ Bp,
                                        int rowBase, int colBase, int k0, int tid)
{
#pragma unroll
    for (int i = 0; i < 4; i++) {      // A: 128 rows x 8 chunks (row = 128B)
        int c = tid + i * 256;
        int row = c >> 3, kc = c & 7;
        uint32_t dst = st + (row << 7) + (((kc ^ row) & 7) << 4);
        cp_async16(dst, A + (size_t)(rowBase + row) * D_FF + k0 + (kc << 3));
    }
#pragma unroll
    for (int i = 0; i < 4; i++) {      // B: 64 k-rows x 16 chunks (row = 256B)
        int c = tid + i * 256;
        int row = c >> 4, nc = c & 15;
        uint32_t dst = st + DN_ABYTES + (row << 8) +
                       ((((nc ^ row) & 7) | (nc & 8)) << 4);
        cp_async16(dst, Bp + (size_t)(k0 + row) * D_MODEL + colBase + (nc << 3));
    }
}

__global__ __launch_bounds__(256, 2)
void dn_fused(const __half* __restrict__ He, const __half* __restrict__ Hs,
              const __half* __restrict__ Wc, float* __restrict__ out,
              const int* __restrict__ labels, const float* __restrict__ w)
{
    extern __shared__ char smem[];
    const uint32_t sb = smem_u32(smem);
    const int tid = threadIdx.x, lane = tid & 31, warp = tid >> 5;
    const int rowBase = blockIdx.y * 128, colBase = blockIdx.x * 128;
    const int batch = rowBase / SEQ;

    const int wm = (warp >> 1) * 32, wn = (warp & 1) * 64;
    const int lr = lane >> 2, lc = lane & 3;
    const int hi = lane >> 4;

    float acc[2][8][4];
#pragma unroll
    for (int mt = 0; mt < 2; mt++)
#pragma unroll
        for (int nt = 0; nt < 8; nt++)
#pragma unroll
            for (int i = 0; i < 4; i++) acc[mt][nt][i] = 0.f;

    const int aRow = wm + (lane & 15);
    const uint32_t aOff = (uint32_t)aRow << 7;
    const uint32_t a_r7 = aRow & 7;
    const uint32_t bRowOff = (uint32_t)(lane & 15) << 8;
    const uint32_t b_r7 = lane & 7;
    uint32_t ncSw[4];
#pragma unroll
    for (int p = 0; p < 4; p++) {
        int nchunk = (wn >> 3) + p * 2 + hi;
        ncSw[p] = (uint32_t)((nchunk & 8) | ((nchunk ^ b_r7) & 7)) << 4;
    }

    const float w0 = w[batch * 2 + 0], w1 = w[batch * 2 + 1];
    const int T = D_FF / 64;  // 64 stages per phase

    for (int ph = 0; ph < 2; ph++) {
        const __half* A  = ph ? Hs : He;
        const __half* Bp = Wc + (size_t)(ph ? 5 : labels[batch]) * WSLOT;

        dn_fill(sb, A, Bp, rowBase, colBase, 0, tid);             CP_COMMIT();
        dn_fill(sb + DN_STAGE, A, Bp, rowBase, colBase, 64, tid); CP_COMMIT();

        int buf = 0;
        for (int t = 0; t < T; t++) {
            CP_WAIT1();
            __syncthreads();
            const uint32_t base  = sb + (uint32_t)buf * DN_STAGE;
            const uint32_t aBase = base + aOff;
            const uint32_t bBase = base + DN_ABYTES + bRowOff;

            const int tn = t + 2;
            if (tn < T) {
                int nb = buf + 2; if (nb >= 3) nb -= 3;
                dn_fill(sb + (uint32_t)nb * DN_STAGE, A, Bp,
                        rowBase, colBase, tn * 64, tid);
            }
            CP_COMMIT();

#pragma unroll
            for (int ks = 0; ks < 4; ks++) {
                uint32_t a[2][4], b[4][4];
                const uint32_t csw = (uint32_t)(((ks * 2 + hi) ^ (int)a_r7) << 4);
                ldsm4(a[0], aBase + csw);
                ldsm4(a[1], aBase + (16u << 7) + csw);
                const uint32_t bk = bBase + (uint32_t)ks * 4096;
#pragma unroll
                for (int p = 0; p < 4; p++) ldsm4t(b[p], bk + ncSw[p]);
#pragma unroll
                for (int mt = 0; mt < 2; mt++)
#pragma unroll
                    for (int nt = 0; nt < 8; nt++)
                        mma16816(acc[mt][nt], a[mt], &b[nt >> 1][(nt & 1) * 2]);
            }
            buf++; if (buf == 3) buf = 0;
        }

        CP_WAIT0();
        __syncthreads();   // drain before phase-2 refill of buffer 0

        if (ph == 0) {
            const float r = w0 / w1;   // softmax(2) -> w1 in (0,1), never 0
#pragma unroll
            for (int mt = 0; mt < 2; mt++)
#pragma unroll
                for (int nt = 0; nt < 8; nt++)
#pragma unroll
                    for (int i = 0; i < 4; i++) acc[mt][nt][i] *= r;
        }
    }

    // ---- epilogue: out = w1 * acc ----
#pragma unroll
    for (int mt = 0; mt < 2; mt++) {
        const int r0 = rowBase + wm + mt * 16 + lr;
#pragma unroll
        for (int nt = 0; nt < 8; nt++) {
            const int c = colBase + wn + nt * 8 + lc * 2;
            const size_t i0 = (size_t)r0 * D_MODEL + c;
            const size_t i1 = i0 + (size_t)8 * D_MODEL;
            *(float2*)(out + i0) =
                make_float2(w1 * acc[mt][nt][0], w1 * acc[mt][nt][1]);
            *(float2*)(out + i1) =
                make_float2(w1 * acc[mt][nt][2], w1 * acc[mt][nt][3]);
        }
    }
}

// ---------------- conversions ---------------------------------------------------
__global__ __launch_bounds__(256)
void cvt_f16(const float* __restrict__ in, __half* __restrict__ out, size_t n)
{
    size_t i = ((size_t)blockIdx.x * 256 + threadIdx.x) * 8;
    if (i >= n) return;
    float4 v0 = *(const float4*)(in + i);
    float4 v1 = *(const float4*)(in + i + 4);
    __half2* o = (__half2*)(out + i);
    o[0] = __floats2half2_rn(v0.x, v0.y);
    o[1] = __floats2half2_rn(v0.z, v0.w);
    o[2] = __floats2half2_rn(v1.x, v1.y);
    o[3] = __floats2half2_rn(v1.z, v1.w);
}

// expert(5 slots) + shared(1 slot) -> 6-slot fp16 buffer
__global__ __launch_bounds__(256)
void cvt_w(const float* __restrict__ e, const float* __restrict__ s,
           __half* __restrict__ dst)
{
    const size_t nE = 5 * WSLOT;
    size_t i = ((size_t)blockIdx.x * 256 + threadIdx.x) * 8;
    const float* src = (i < nE) ? e + i : s + (i - nE);
    float4 v0 = *(const float4*)(src);
    float4 v1 = *(const float4*)(src + 4);
    __half2* o = (__half2*)(dst + i);
    o[0] = __floats2half2_rn(v0.x, v0.y);
    o[1] = __floats2half2_rn(v0.z, v0.w);
    o[2] = __floats2half2_rn(v1.x, v1.y);
    o[3] = __floats2half2_rn(v1.z, v1.w);
}

// ---------------- row-0 GEMV (k-split 4) ---------------------------------------
__global__ __launch_bounds__(256)
void row0_kernel(const __half* __restrict__ H, const __half* __restrict__ H2,
                 const __half* __restrict__ Wc, const int* __restrict__ lbl,
                 float* __restrict__ gp)
{
    const int b = blockIdx.y, z = blockIdx.z;
    const int j = blockIdx.x * 256 + threadIdx.x;   // 0..2047
    const bool sh = j >= D_MODEL;
    const int col = j & (D_MODEL - 1);
    const __half* A = (sh ? H2 : H) + (size_t)b * SEQ * D_FF + z * 1024;
    const __half* Wp = Wc + (size_t)(sh ? 5 : lbl[b]) * WSLOT +
                       (size_t)z * 1024 * D_MODEL + col;
    float acc = 0.f;
#pragma unroll 8
    for (int k = 0; k < 1024; k++)
        acc = fmaf(__half2float(A[k]), __half2float(Wp[(size_t)k * D_MODEL]), acc);
    gp[((size_t)z * BATCH + b) * 2 * D_MODEL + j] = acc;
}

// ---------------- gate ----------------------------------------------------------
__global__ __launch_bounds__(256)
void gate_kernel(const float* __restrict__ gp,
                 const float* __restrict__ g0, const float* __restrict__ g1,
                 float* __restrict__ w)
{
    int b = blockIdx.x;
    const size_t stride = (size_t)BATCH * 2 * D_MODEL;
    const float* gi = gp + (size_t)b * 2 * D_MODEL;
    float h[4] = {0.f, 0.f, 0.f, 0.f};
    for (int k = 0; k < 2 * D_MODEL; k++) {
        float xin = gi[k] + gi[stride + k] + gi[2 * stride + k] + gi[3 * stride + k];
        const float* grow = g0 + (size_t)k * D_MODEL;
#pragma unroll
        for (int u = 0; u < 4; u++)
            h[u] = fmaf(xin, grow[threadIdx.x + 256 * u], h[u]);
    }
    float l0 = 0.f, l1 = 0.f;
#pragma unroll
    for (int u = 0; u < 4; u++) {
        int j = threadIdx.x + 256 * u;
        float hr = fmaxf(h[u], 0.f);
        l0 = fmaf(hr, g1[j * 2 + 0], l0);
        l1 = fmaf(hr, g1[j * 2 + 1], l1);
    }
    __shared__ float red0[256], red1[256];
    red0[threadIdx.x] = l0;
    red1[threadIdx.x] = l1;
    __syncthreads();
    for (int s = 128; s > 0; s >>= 1) {
        if (threadIdx.x < s) {
            red0[threadIdx.x] += red0[threadIdx.x + s];
            red1[threadIdx.x] += red1[threadIdx.x + s];
        }
        __syncthreads();
    }
    if (threadIdx.x == 0) {
        float a = red0[0], c = red1[0];
        float m  = fmaxf(a, c);
        float e0 = expf(a - m), e1 = expf(c - m);
        float inv = 1.f / (e0 + e1);
        w[b * 2 + 0] = e0 * inv;
        w[b * 2 + 1] = e1 * inv;
    }
}

// ---------------- launch -------------------------------------------------------
extern "C" void kernel_launch(void* const* d_in, const int* in_sizes, int n_in,
                              void* d_out, int out_size)
{
    const float* X    = (const float*)d_in[0];
    const int*   lbl  = (const int*)  d_in[1];
    const float* Wi0  = (const float*)d_in[2];
    const float* Wi1  = (const float*)d_in[3];
    const float* Wo   = (const float*)d_in[4];
    const float* sWi0 = (const float*)d_in[5];
    const float* sWi1 = (const float*)d_in[6];
    const float* sWo  = (const float*)d_in[7];
    const float* G0   = (const float*)d_in[8];
    const float* G1   = (const float*)d_in[9];
    float* out = (float*)d_out;

    __half *Xh, *H, *H2, *Wa, *Wb, *Wc;
    float *gp, *W;
    cudaGetSymbolAddress((void**)&Xh, g_Xh);
    cudaGetSymbolAddress((void**)&H,  g_H);
    cudaGetSymbolAddress((void**)&H2, g_H2);
    cudaGetSymbolAddress((void**)&Wa, g_Wa);
    cudaGetSymbolAddress((void**)&Wb, g_Wb);
    cudaGetSymbolAddress((void**)&Wc, g_Wc);
    cudaGetSymbolAddress((void**)&gp, g_gp);
    cudaGetSymbolAddress((void**)&W,  g_W);

    cudaFuncSetAttribute(up_fused, cudaFuncAttributeMaxDynamicSharedMemorySize, UP_SMEM);
    cudaFuncSetAttribute(dn_fused, cudaFuncAttributeMaxDynamicSharedMemorySize, DN_SMEM);

    const size_t nX = (size_t)M_TOT * D_MODEL;
    const unsigned wBlocks = (unsigned)(6 * WSLOT / 2048);   // 12288
    dim3 blk(256);
    dim3 grid_up(D_FF / 64, M_TOT / 128, 2);      // (64,128,2)
    dim3 grid_dn(D_MODEL / 128, M_TOT / 128);     // (8,128)

    // ---- conversions ----
    cvt_f16<<<(unsigned)(nX / 2048), blk>>>(X, Xh, nX);
    cvt_w<<<wBlocks, blk>>>(Wi0, sWi0, Wa);
    cvt_w<<<wBlocks, blk>>>(Wi1, sWi1, Wb);
    cvt_w<<<wBlocks, blk>>>(Wo,  sWo,  Wc);

    // ---- both up projections in one launch ----
    up_fused<<<grid_up, blk, UP_SMEM>>>(Xh, Wa, Wb, H, H2, lbl);

    // ---- gate from first-token rows ----
    row0_kernel<<<dim3(8, BATCH, 4), blk>>>(H, H2, Wc, lbl, gp);
    gate_kernel<<<BATCH, blk>>>(gp, G0, G1, W);

    // ---- fused down GEMM: out = w0*E + w1*S ----
    dn_fused<<<grid_dn, blk, DN_SMEM>>>(H, H2, Wc, out, lbl, W);
}